// round 6
// baseline (speedup 1.0000x reference)
#include <cuda_runtime.h>

// ---------------- problem constants ----------------
#define N_TOK   16384
#define DIM     1024
#define HEADS   8
#define DHEAD   64
#define HD      (HEADS * DHEAD)   // 512
#define QKVW    (3 * HD)          // 1536
#define WSZ     128
#define NWIN    (N_TOK / WSZ)     // 128

// ---------------- scratch (static device arrays; no allocs allowed) ----------------
__device__ float g_qkv[(size_t)N_TOK * QKVW];    // GEMM1 out (fp32)
__device__ float g_attn[(size_t)N_TOK * HD];     // attention out (tf32-rounded fp32)
__device__ float g_xc[(size_t)N_TOK * DIM];      // x rounded to tf32
__device__ float g_wqkvc[(size_t)DIM * QKVW];    // w_qkv rounded to tf32
__device__ float g_woutc[(size_t)HD * DIM];      // w_out rounded to tf32

// ---------------- helpers ----------------
__device__ __forceinline__ unsigned f2tf32(float x) {
    unsigned r;
    asm("cvt.rna.tf32.f32 %0, %1;" : "=r"(r) : "f"(x));
    return r;
}

__device__ __forceinline__ void mma_tf32(float c[4], const unsigned a[4],
                                         unsigned b0, unsigned b1) {
    asm volatile(
        "mma.sync.aligned.m16n8k8.row.col.f32.tf32.tf32.f32 "
        "{%0,%1,%2,%3}, {%4,%5,%6,%7}, {%8,%9}, {%0,%1,%2,%3};"
        : "+f"(c[0]), "+f"(c[1]), "+f"(c[2]), "+f"(c[3])
        : "r"(a[0]), "r"(a[1]), "r"(a[2]), "r"(a[3]), "r"(b0), "r"(b1));
}

__global__ void cvt_tf32_kernel(const float4* __restrict__ in,
                                float4* __restrict__ out, int n4)
{
    int i = blockIdx.x * blockDim.x + threadIdx.x;
    if (i < n4) {
        float4 v = in[i];
        v.x = __uint_as_float(f2tf32(v.x));
        v.y = __uint_as_float(f2tf32(v.y));
        v.z = __uint_as_float(f2tf32(v.z));
        v.w = __uint_as_float(f2tf32(v.w));
        out[i] = v;
    }
}

// ---------------- TF32 tensor-core GEMM, 64x64 warp tiles ----------------
// C[M,N] = A[M,K] @ B[K,N] (+bias). CTA tile 128x128x32, 4 warps (2x2),
// warp tile 64x64, 3-stage cp.async pipeline, 128 threads.
// Element swizzles (store == read):
//   A[m][k]  at float offset m*32  + (k ^ (4*(m&7)))
//   B[k][n]  at float offset 4096 + k*128 + (n ^ (8*(k&7)))
// Stage s at float offset s*8192 (32 KB/stage, 96 KB total).

#define CPA16(dst, src) \
    asm volatile("cp.async.cg.shared.global [%0], [%1], 16;" :: "r"(dst), "l"(src))

#define GEMM_SMEM_BYTES (3 * 32768)

template <bool WITH_BIAS>
__global__ __launch_bounds__(128)
void tf32gemm(const float* __restrict__ A, const float* __restrict__ B,
              const float* __restrict__ bias, float* __restrict__ C,
              int M, int N, int K)
{
    extern __shared__ float sm[];

    const int tid  = threadIdx.x;
    const int lane = tid & 31;
    const int wid  = tid >> 5;          // 0..3
    const int wm   = wid >> 1;          // 0..1
    const int wn   = wid & 1;           // 0..1
    const int g    = lane >> 2;         // 0..7
    const int tg   = lane & 3;          // 0..3

    const int row0 = blockIdx.y * 128;
    const int col0 = blockIdx.x * 128;

    // loader mapping (16B granules, 8 A + 8 B per thread)
    const int ar = tid >> 2;            // A row base 0..31
    const int ak = tid & 3;             // A k4 base
    const int br = tid >> 5;            // B row base 0..3
    const int bn = tid & 31;            // B n4

    const unsigned smBase = (unsigned)__cvta_generic_to_shared(sm);

    float acc[4][8][4];
#pragma unroll
    for (int mi = 0; mi < 4; ++mi)
#pragma unroll
        for (int ni = 0; ni < 8; ++ni)
#pragma unroll
            for (int r = 0; r < 4; ++r) acc[mi][ni][r] = 0.f;

    const int nk = K / 32;

    auto issue = [&](int kt, int s) {
        const unsigned sb = smBase + (unsigned)s * 32768u;
#pragma unroll
        for (int p = 0; p < 8; ++p) {                       // A: 128x32
            int r  = ar + 32 * (p >> 1);
            int k4 = ak + 4 * (p & 1);
            unsigned dst = sb + 4u * (unsigned)(r * 32 + 4 * (k4 ^ (r & 7)));
            CPA16(dst, A + (size_t)(row0 + r) * K + kt * 32 + 4 * k4);
        }
#pragma unroll
        for (int p = 0; p < 8; ++p) {                       // B: 32x128
            int r = br + 4 * p;
            unsigned dst = sb + 4u * (unsigned)(4096 + r * 128 + 4 * (bn ^ (2 * (r & 7))));
            CPA16(dst, B + (size_t)(kt * 32 + r) * N + col0 + 4 * bn);
        }
        asm volatile("cp.async.commit_group;");
    };

    issue(0, 0);
    issue(1, 1);

    for (int kt = 0; kt < nk; ++kt) {
        const int s = kt % 3;
        if (kt + 1 < nk) {
            asm volatile("cp.async.wait_group 1;");
        } else {
            asm volatile("cp.async.wait_group 0;");
        }
        __syncthreads();
        if (kt + 2 < nk) issue(kt + 2, (kt + 2) % 3);

        const float* as = sm + s * 8192;
        const float* bs = sm + s * 8192 + 4096;

#pragma unroll
        for (int ksu = 0; ksu < 4; ++ksu) {
            const int k0 = 8 * ksu + tg;
            const int sw = 4 * g;
            unsigned a[4][4];
#pragma unroll
            for (int mi = 0; mi < 4; ++mi) {
                int m = wm * 64 + mi * 16 + g;
                a[mi][0] = __float_as_uint(as[m * 32 + (k0 ^ sw)]);
                a[mi][1] = __float_as_uint(as[(m + 8) * 32 + (k0 ^ sw)]);
                a[mi][2] = __float_as_uint(as[m * 32 + ((k0 + 4) ^ sw)]);
                a[mi][3] = __float_as_uint(as[(m + 8) * 32 + ((k0 + 4) ^ sw)]);
            }
            unsigned b[8][2];
            const int sb0 = 8 * (k0 & 7);
            const int sb1 = 8 * ((k0 + 4) & 7);
#pragma unroll
            for (int ni = 0; ni < 8; ++ni) {
                int n0 = wn * 64 + ni * 8 + g;
                b[ni][0] = __float_as_uint(bs[k0 * 128 + (n0 ^ sb0)]);
                b[ni][1] = __float_as_uint(bs[(k0 + 4) * 128 + (n0 ^ sb1)]);
            }
#pragma unroll
            for (int mi = 0; mi < 4; ++mi)
#pragma unroll
                for (int ni = 0; ni < 8; ++ni)
                    mma_tf32(acc[mi][ni], a[mi], b[ni][0], b[ni][1]);
        }
        __syncthreads();
    }

    // epilogue
#pragma unroll
    for (int ni = 0; ni < 8; ++ni) {
        int col = col0 + wn * 64 + ni * 8 + 2 * tg;
        float bx = 0.f, by = 0.f;
        if (WITH_BIAS) { bx = bias[col]; by = bias[col + 1]; }
#pragma unroll
        for (int mi = 0; mi < 4; ++mi) {
            int row = row0 + wm * 64 + mi * 16 + g;
            float2 v0 = make_float2(acc[mi][ni][0] + bx, acc[mi][ni][1] + by);
            float2 v1 = make_float2(acc[mi][ni][2] + bx, acc[mi][ni][3] + by);
            *reinterpret_cast<float2*>(&C[(size_t)row * N + col]) = v0;
            *reinterpret_cast<float2*>(&C[(size_t)(row + 8) * N + col]) = v1;
        }
    }
}

// ---------------- tensor-core attention (unchanged from round 4) ----------------
#define KS_STRIDE 68
#define VS_STRIDE 72
#define ATTN_SMEM ((256 * KS_STRIDE + 256 * VS_STRIDE) * sizeof(float))  // 143360

__global__ __launch_bounds__(256, 1)
void attn_mma_kernel(const float* __restrict__ qkv, float* __restrict__ o)
{
    extern __shared__ float smA[];
    float* ks = smA;                      // [256][68] (Q staging first, then K)
    float* vs = smA + 256 * KS_STRIDE;    // [256][72]

    const int w    = blockIdx.x;
    const int h    = blockIdx.y;
    const int tid  = threadIdx.x;
    const int lane = tid & 31;
    const int wq   = tid >> 5;            // 0..7
    const int g    = lane >> 2;           // 0..7
    const int tg   = lane & 3;            // 0..3
    const int m0   = wq * 16;
    const int tok0 = w * WSZ;

    for (int i = tid; i < WSZ * 16; i += 256) {
        int row = i >> 4, c4 = (i & 15) * 4;
        float4 v = *reinterpret_cast<const float4*>(
            &qkv[(size_t)(tok0 + row) * QKVW + h * DHEAD + c4]);
        float4 r;
        r.x = __uint_as_float(f2tf32(v.x * 0.125f));
        r.y = __uint_as_float(f2tf32(v.y * 0.125f));
        r.z = __uint_as_float(f2tf32(v.z * 0.125f));
        r.w = __uint_as_float(f2tf32(v.w * 0.125f));
        *reinterpret_cast<float4*>(&ks[row * KS_STRIDE + c4]) = r;
    }
    __syncthreads();

    unsigned qa[8][4];
#pragma unroll
    for (int kt = 0; kt < 8; ++kt) {
        int k0 = 8 * kt + tg;
        qa[kt][0] = __float_as_uint(ks[(m0 + g) * KS_STRIDE + k0]);
        qa[kt][1] = __float_as_uint(ks[(m0 + g + 8) * KS_STRIDE + k0]);
        qa[kt][2] = __float_as_uint(ks[(m0 + g) * KS_STRIDE + k0 + 4]);
        qa[kt][3] = __float_as_uint(ks[(m0 + g + 8) * KS_STRIDE + k0 + 4]);
    }
    __syncthreads();

    for (int i = tid; i < 256 * 16; i += 256) {
        int j = i >> 4, c4 = (i & 15) * 4;
        float4 kv = make_float4(0.f, 0.f, 0.f, 0.f);
        float4 vv = make_float4(0.f, 0.f, 0.f, 0.f);
        if (!(w == 0 && j < WSZ)) {
            size_t tok = (size_t)(tok0 - WSZ + j);
            kv = *reinterpret_cast<const float4*>(&qkv[tok * QKVW +     HD + h * DHEAD + c4]);
            vv = *reinterpret_cast<const float4*>(&qkv[tok * QKVW + 2 * HD + h * DHEAD + c4]);
        }
        float4 kr, vr;
        kr.x = __uint_as_float(f2tf32(kv.x)); kr.y = __uint_as_float(f2tf32(kv.y));
        kr.z = __uint_as_float(f2tf32(kv.z)); kr.w = __uint_as_float(f2tf32(kv.w));
        vr.x = __uint_as_float(f2tf32(vv.x)); vr.y = __uint_as_float(f2tf32(vv.y));
        vr.z = __uint_as_float(f2tf32(vv.z)); vr.w = __uint_as_float(f2tf32(vv.w));
        *reinterpret_cast<float4*>(&ks[j * KS_STRIDE + c4]) = kr;
        *reinterpret_cast<float4*>(&vs[j * VS_STRIDE + c4]) = vr;
    }
    __syncthreads();

    float s[32][4];
#pragma unroll
    for (int nt = 0; nt < 32; ++nt) {
        s[nt][0] = 0.f; s[nt][1] = 0.f; s[nt][2] = 0.f; s[nt][3] = 0.f;
        const int n0 = 8 * nt + g;
#pragma unroll
        for (int kt = 0; kt < 8; ++kt) {
            int k0 = 8 * kt + tg;
            unsigned b0 = __float_as_uint(ks[n0 * KS_STRIDE + k0]);
            unsigned b1 = __float_as_uint(ks[n0 * KS_STRIDE + k0 + 4]);
            mma_tf32(s[nt], qa[kt], b0, b1);
        }
    }

    const int i_lo = m0 + g, i_hi = i_lo + 8;
    float mx0 = -3.0e38f, mx1 = -3.0e38f;
#pragma unroll
    for (int nt = 0; nt < 32; ++nt) {
        int j0 = 8 * nt + 2 * tg, j1 = j0 + 1;
        if (j0 > i_lo + WSZ) s[nt][0] = -1e10f;
        if (j1 > i_lo + WSZ) s[nt][1] = -1e10f;
        if (j0 > i_hi + WSZ) s[nt][2] = -1e10f;
        if (j1 > i_hi + WSZ) s[nt][3] = -1e10f;
        mx0 = fmaxf(mx0, fmaxf(s[nt][0], s[nt][1]));
        mx1 = fmaxf(mx1, fmaxf(s[nt][2], s[nt][3]));
    }
    mx0 = fmaxf(mx0, __shfl_xor_sync(0xffffffffu, mx0, 1));
    mx0 = fmaxf(mx0, __shfl_xor_sync(0xffffffffu, mx0, 2));
    mx1 = fmaxf(mx1, __shfl_xor_sync(0xffffffffu, mx1, 1));
    mx1 = fmaxf(mx1, __shfl_xor_sync(0xffffffffu, mx1, 2));

    float l0 = 0.f, l1 = 0.f;
#pragma unroll
    for (int nt = 0; nt < 32; ++nt) {
        float p0 = __expf(s[nt][0] - mx0);
        float p1 = __expf(s[nt][1] - mx0);
        float p2 = __expf(s[nt][2] - mx1);
        float p3 = __expf(s[nt][3] - mx1);
        l0 += p0 + p1;
        l1 += p2 + p3;
        s[nt][0] = __uint_as_float(f2tf32(p0));
        s[nt][1] = __uint_as_float(f2tf32(p1));
        s[nt][2] = __uint_as_float(f2tf32(p2));
        s[nt][3] = __uint_as_float(f2tf32(p3));
    }
    l0 += __shfl_xor_sync(0xffffffffu, l0, 1);
    l0 += __shfl_xor_sync(0xffffffffu, l0, 2);
    l1 += __shfl_xor_sync(0xffffffffu, l1, 1);
    l1 += __shfl_xor_sync(0xffffffffu, l1, 2);

    float ov[8][4];
#pragma unroll
    for (int nt = 0; nt < 8; ++nt) {
        ov[nt][0] = 0.f; ov[nt][1] = 0.f; ov[nt][2] = 0.f; ov[nt][3] = 0.f;
    }

#pragma unroll
    for (int kj = 0; kj < 32; ++kj) {
        int src0 = (lane & ~3) | (tg >> 1);
        int src2 = src0 + 2;
        float v00 = __shfl_sync(0xffffffffu, s[kj][0], src0);
        float v01 = __shfl_sync(0xffffffffu, s[kj][1], src0);
        float v10 = __shfl_sync(0xffffffffu, s[kj][2], src0);
        float v11 = __shfl_sync(0xffffffffu, s[kj][3], src0);
        float v20 = __shfl_sync(0xffffffffu, s[kj][0], src2);
        float v21 = __shfl_sync(0xffffffffu, s[kj][1], src2);
        float v30 = __shfl_sync(0xffffffffu, s[kj][2], src2);
        float v31 = __shfl_sync(0xffffffffu, s[kj][3], src2);
        bool odd = (tg & 1);
        unsigned a[4];
        a[0] = __float_as_uint(odd ? v01 : v00);
        a[1] = __float_as_uint(odd ? v11 : v10);
        a[2] = __float_as_uint(odd ? v21 : v20);
        a[3] = __float_as_uint(odd ? v31 : v30);

        const int j0 = 8 * kj + tg;
#pragma unroll
        for (int nt = 0; nt < 8; ++nt) {
            unsigned b0 = __float_as_uint(vs[j0 * VS_STRIDE + 8 * nt + g]);
            unsigned b1 = __float_as_uint(vs[(j0 + 4) * VS_STRIDE + 8 * nt + g]);
            mma_tf32(ov[nt], a, b0, b1);
        }
    }

    float inv0 = 1.f / l0, inv1 = 1.f / l1;
    const int row_lo = tok0 + m0 + g;
#pragma unroll
    for (int nt = 0; nt < 8; ++nt) {
        int col = h * DHEAD + 8 * nt + 2 * tg;
        float2 w0, w1;
        w0.x = __uint_as_float(f2tf32(ov[nt][0] * inv0));
        w0.y = __uint_as_float(f2tf32(ov[nt][1] * inv0));
        w1.x = __uint_as_float(f2tf32(ov[nt][2] * inv1));
        w1.y = __uint_as_float(f2tf32(ov[nt][3] * inv1));
        *reinterpret_cast<float2*>(&o[(size_t)row_lo * HD + col]) = w0;
        *reinterpret_cast<float2*>(&o[(size_t)(row_lo + 8) * HD + col]) = w1;
    }
}

// ---------------- launch ----------------
extern "C" void kernel_launch(void* const* d_in, const int* in_sizes, int n_in,
                              void* d_out, int out_size)
{
    (void)in_sizes; (void)n_in; (void)out_size;
    const float* x     = (const float*)d_in[0];  // [16384, 1024]
    const float* w_qkv = (const float*)d_in[1];  // [1024, 1536]
    const float* w_out = (const float*)d_in[2];  // [512, 1024]
    const float* b_out = (const float*)d_in[3];  // [1024]
    float*       out   = (float*)d_out;          // [16384, 1024]

    float *qkv = nullptr, *attn = nullptr, *xc = nullptr, *wqkvc = nullptr, *woutc = nullptr;
    cudaGetSymbolAddress((void**)&qkv,   g_qkv);
    cudaGetSymbolAddress((void**)&attn,  g_attn);
    cudaGetSymbolAddress((void**)&xc,    g_xc);
    cudaGetSymbolAddress((void**)&wqkvc, g_wqkvc);
    cudaGetSymbolAddress((void**)&woutc, g_woutc);

    cudaFuncSetAttribute(tf32gemm<false>, cudaFuncAttributeMaxDynamicSharedMemorySize, GEMM_SMEM_BYTES);
    cudaFuncSetAttribute(tf32gemm<true>,  cudaFuncAttributeMaxDynamicSharedMemorySize, GEMM_SMEM_BYTES);
    cudaFuncSetAttribute(attn_mma_kernel, cudaFuncAttributeMaxDynamicSharedMemorySize, (int)ATTN_SMEM);

    // 0) round inputs to tf32 (RN)
    {
        int n4;
        n4 = N_TOK * DIM / 4;
        cvt_tf32_kernel<<<(n4 + 255) / 256, 256>>>((const float4*)x, (float4*)xc, n4);
        n4 = DIM * QKVW / 4;
        cvt_tf32_kernel<<<(n4 + 255) / 256, 256>>>((const float4*)w_qkv, (float4*)wqkvc, n4);
        n4 = HD * DIM / 4;
        cvt_tf32_kernel<<<(n4 + 255) / 256, 256>>>((const float4*)w_out, (float4*)woutc, n4);
    }

    // 1) QKV projection: [16384,1024] @ [1024,1536]
    {
        dim3 grid(QKVW / 128, N_TOK / 128);
        tf32gemm<false><<<grid, 128, GEMM_SMEM_BYTES>>>(xc, wqkvc, nullptr, qkv, N_TOK, QKVW, DIM);
    }

    // 2) windowed look-back attention
    {
        dim3 grid(NWIN, HEADS);
        attn_mma_kernel<<<grid, 256, ATTN_SMEM>>>(qkv, attn);
    }

    // 3) output projection: [16384,512] @ [512,1024] + bias
    {
        dim3 grid(DIM / 128, N_TOK / 128);
        tf32gemm<true><<<grid, 128, GEMM_SMEM_BYTES>>>(attn, woutc, b_out, out, N_TOK, DIM, HD);
    }
}

// round 8
// speedup vs baseline: 1.8903x; 1.8903x over previous
#include <cuda_runtime.h>
#include <cuda_fp16.h>
#include <cstdint>

// ---------------- problem constants ----------------
#define N_TOK   16384
#define DIM     1024
#define HEADS   8
#define DHEAD   64
#define HD      (HEADS * DHEAD)   // 512
#define QKVW    (3 * HD)          // 1536
#define WSZ     128
#define NWIN    (N_TOK / WSZ)     // 128

// ---------------- scratch ----------------
__device__ __half g_xh[(size_t)N_TOK * DIM];      // x -> half
__device__ __half g_wqkvT[(size_t)QKVW * DIM];    // w_qkv^T half  [1536][1024]
__device__ __half g_woutT[(size_t)DIM * HD];      // w_out^T half  [1024][512]
__device__ __half g_qkvh[(size_t)N_TOK * QKVW];   // GEMM1 out half
__device__ __half g_attnh[(size_t)N_TOK * HD];    // attention out half

// ---------------- helpers ----------------
__device__ __forceinline__ unsigned h2u(__half2 h) {
    return *reinterpret_cast<unsigned*>(&h);
}

__device__ __forceinline__ void mma_f16(float c[4], unsigned a0, unsigned a1,
                                        unsigned a2, unsigned a3,
                                        unsigned b0, unsigned b1) {
    asm volatile(
        "mma.sync.aligned.m16n8k16.row.col.f32.f16.f16.f32 "
        "{%0,%1,%2,%3}, {%4,%5,%6,%7}, {%8,%9}, {%0,%1,%2,%3};"
        : "+f"(c[0]), "+f"(c[1]), "+f"(c[2]), "+f"(c[3])
        : "r"(a0), "r"(a1), "r"(a2), "r"(a3), "r"(b0), "r"(b1));
}

__global__ void cvt_f2h(const float4* __restrict__ in,
                        __half2* __restrict__ out, int n4)
{
    int i = blockIdx.x * blockDim.x + threadIdx.x;
    if (i < n4) {
        float4 v = in[i];
        out[2 * i + 0] = __floats2half2_rn(v.x, v.y);
        out[2 * i + 1] = __floats2half2_rn(v.z, v.w);
    }
}

// in[R][C] fp32 -> out[C][R] half. block (32,8), grid (C/32, R/32).
__global__ void transpose_f2h(const float* __restrict__ in,
                              __half* __restrict__ out, int R, int C)
{
    __shared__ float t[32][33];
    int bx = blockIdx.x * 32, by = blockIdx.y * 32;
    int x = bx + threadIdx.x;
#pragma unroll
    for (int i = 0; i < 32; i += 8) {
        int y = by + threadIdx.y + i;
        t[threadIdx.y + i][threadIdx.x] = in[(size_t)y * C + x];
    }
    __syncthreads();
    int xo = by + threadIdx.x;
#pragma unroll
    for (int i = 0; i < 32; i += 8) {
        int yo = bx + threadIdx.y + i;
        out[(size_t)yo * R + xo] = __float2half_rn(t[threadIdx.x][threadIdx.y + i]);
    }
}

// ---------------- FP16 tensor-core GEMM ----------------
// C[M,N] = A[M,K] @ Bt[N,K]^T (+bias). A, Bt half row-major.
// CTA 128x128x64(halves), 8 warps 2x4 (warp tile 64x32), 3-stage cp.async.
// smem tile layout (halves): row r (A: m, B: n) of 64 halves = 8 x 16B chunks,
// chunk c stored at c ^ (r&7). A at stage base, B at stage base + 8192 halves.
#define CPA16(dst, src) \
    asm volatile("cp.async.cg.shared.global [%0], [%1], 16;" :: "r"(dst), "l"(src))

#define HSTAGE 16384                       // halves per stage
#define HG_SMEM (3 * HSTAGE * 2)           // 98304 bytes

template <bool WITH_BIAS, bool HALF_OUT>
__global__ __launch_bounds__(256, 2)
void h16gemm(const __half* __restrict__ A, const __half* __restrict__ Bt,
             const float* __restrict__ bias, void* __restrict__ Cout,
             int M, int N, int K)
{
    extern __shared__ __half hsm[];
    const unsigned smBase = (unsigned)__cvta_generic_to_shared(hsm);

    const int tid  = threadIdx.x;
    const int lane = tid & 31;
    const int wid  = tid >> 5;
    const int wm   = wid >> 2;          // 0..1
    const int wn   = wid & 3;           // 0..3
    const int g    = lane >> 2;         // 0..7
    const int tg   = lane & 3;          // 0..3

    const int row0 = blockIdx.y * 128;
    const int col0 = blockIdx.x * 128;
    const int NKT  = K / 64;

    float acc[4][4][4];
#pragma unroll
    for (int mi = 0; mi < 4; ++mi)
#pragma unroll
        for (int ni = 0; ni < 4; ++ni)
#pragma unroll
            for (int r = 0; r < 4; ++r) acc[mi][ni][r] = 0.f;

    auto issue = [&](int kt, int s) {
        const unsigned sb = smBase + (unsigned)s * (HSTAGE * 2);
#pragma unroll
        for (int p = 0; p < 4; ++p) {       // A: 1024 chunks / 256 thr
            int idx = p * 256 + tid;
            int r = idx >> 3, c = idx & 7;
            CPA16(sb + (unsigned)(r * 128 + ((c ^ (r & 7)) * 16)),
                  A + (size_t)(row0 + r) * K + kt * 64 + c * 8);
        }
#pragma unroll
        for (int p = 0; p < 4; ++p) {       // B: 1024 chunks
            int idx = p * 256 + tid;
            int r = idx >> 3, c = idx & 7;
            CPA16(sb + 16384u + (unsigned)(r * 128 + ((c ^ (r & 7)) * 16)),
                  Bt + (size_t)(col0 + r) * K + kt * 64 + c * 8);
        }
        asm volatile("cp.async.commit_group;");
    };

    issue(0, 0);
    issue(1, 1);

    for (int kt = 0; kt < NKT; ++kt) {
        const int s = kt % 3;
        if (kt + 1 < NKT) asm volatile("cp.async.wait_group 1;");
        else              asm volatile("cp.async.wait_group 0;");
        __syncthreads();
        if (kt + 2 < NKT) issue(kt + 2, (kt + 2) % 3);

        const __half* as = hsm + s * HSTAGE;
        const __half* bs = as + 8192;

#pragma unroll
        for (int ks = 0; ks < 4; ++ks) {
            unsigned a[4][4];
#pragma unroll
            for (int mi = 0; mi < 4; ++mi) {
                int m = wm * 64 + mi * 16 + g;
                int base = m * 64 + (((2 * ks) ^ (m & 7)) << 3) + 2 * tg;
                int base1 = m * 64 + (((2 * ks + 1) ^ (m & 7)) << 3) + 2 * tg;
                a[mi][0] = *(const unsigned*)&as[base];
                a[mi][1] = *(const unsigned*)&as[base + 512];
                a[mi][2] = *(const unsigned*)&as[base1];
                a[mi][3] = *(const unsigned*)&as[base1 + 512];
            }
            unsigned b[4][2];
#pragma unroll
            for (int ni = 0; ni < 4; ++ni) {
                int n = wn * 32 + ni * 8 + g;
                int base = n * 64 + (((2 * ks) ^ (n & 7)) << 3) + 2 * tg;
                int base1 = n * 64 + (((2 * ks + 1) ^ (n & 7)) << 3) + 2 * tg;
                b[ni][0] = *(const unsigned*)&bs[base];
                b[ni][1] = *(const unsigned*)&bs[base1];
            }
#pragma unroll
            for (int mi = 0; mi < 4; ++mi)
#pragma unroll
                for (int ni = 0; ni < 4; ++ni)
                    mma_f16(acc[mi][ni], a[mi][0], a[mi][1], a[mi][2], a[mi][3],
                            b[ni][0], b[ni][1]);
        }
        __syncthreads();
    }

    // epilogue
#pragma unroll
    for (int ni = 0; ni < 4; ++ni) {
        int col = col0 + wn * 32 + ni * 8 + 2 * tg;
        float bx = 0.f, by = 0.f;
        if (WITH_BIAS) { bx = bias[col]; by = bias[col + 1]; }
#pragma unroll
        for (int mi = 0; mi < 4; ++mi) {
            int row = row0 + wm * 64 + mi * 16 + g;
            if (HALF_OUT) {
                __half* C = (__half*)Cout;
                __half2 h0 = __floats2half2_rn(acc[mi][ni][0], acc[mi][ni][1]);
                __half2 h1 = __floats2half2_rn(acc[mi][ni][2], acc[mi][ni][3]);
                *reinterpret_cast<__half2*>(&C[(size_t)row * N + col]) = h0;
                *reinterpret_cast<__half2*>(&C[(size_t)(row + 8) * N + col]) = h1;
            } else {
                float* C = (float*)Cout;
                float2 v0 = make_float2(acc[mi][ni][0] + bx, acc[mi][ni][1] + by);
                float2 v1 = make_float2(acc[mi][ni][2] + bx, acc[mi][ni][3] + by);
                *reinterpret_cast<float2*>(&C[(size_t)row * N + col]) = v0;
                *reinterpret_cast<float2*>(&C[(size_t)(row + 8) * N + col]) = v1;
            }
        }
    }
}

// ---------------- FP16 tensor-core attention ----------------
// One CTA per (window, head), 256 threads (8 warps x 16 query rows).
// smem (halves): qs [128][64] swizzled @0; ksm [256][64] swizzled @8192;
//                vsT [64][264] (V transposed, padded) @24576.
#define ATTN_SMEM_H (24576 + 64 * 264)            // halves
#define ATTN_SMEM_B (ATTN_SMEM_H * 2)             // 82944 bytes

__global__ __launch_bounds__(256, 1)
void attn_h16_kernel(const __half* __restrict__ qkv, __half* __restrict__ o)
{
    extern __shared__ __half hs[];
    __half* qs  = hs;
    __half* ksm = hs + 8192;
    __half* vsT = hs + 24576;

    const int w    = blockIdx.x;
    const int h    = blockIdx.y;
    const int tid  = threadIdx.x;
    const int lane = tid & 31;
    const int wq   = tid >> 5;
    const int g    = lane >> 2;
    const int tg   = lane & 3;
    const int m0   = wq * 16;
    const int tok0 = w * WSZ;

    const __half2 qscale = __floats2half2_rn(0.125f, 0.125f);

    // ---- load Q (scaled), swizzled ----
#pragma unroll
    for (int p = 0; p < 4; ++p) {                    // 1024 chunks
        int idx = p * 256 + tid;
        int row = idx >> 3, c = idx & 7;
        uint4 v = *reinterpret_cast<const uint4*>(
            &qkv[(size_t)(tok0 + row) * QKVW + h * DHEAD + c * 8]);
        __half2* hv = reinterpret_cast<__half2*>(&v);
        hv[0] = __hmul2(hv[0], qscale);
        hv[1] = __hmul2(hv[1], qscale);
        hv[2] = __hmul2(hv[2], qscale);
        hv[3] = __hmul2(hv[3], qscale);
        *reinterpret_cast<uint4*>(&qs[row * 64 + ((c ^ (row & 7)) << 3)]) = v;
    }

    // ---- load K (swizzled) and V (transposed into vsT) ----
#pragma unroll
    for (int p = 0; p < 8; ++p) {                    // 2048 chunks
        int idx = p * 256 + tid;
        int j = idx >> 3, c = idx & 7;
        uint4 kv = make_uint4(0, 0, 0, 0), vv = make_uint4(0, 0, 0, 0);
        if (!(w == 0 && j < WSZ)) {
            size_t tok = (size_t)(tok0 - WSZ + j);
            kv = *reinterpret_cast<const uint4*>(&qkv[tok * QKVW +     HD + h * DHEAD + c * 8]);
            vv = *reinterpret_cast<const uint4*>(&qkv[tok * QKVW + 2 * HD + h * DHEAD + c * 8]);
        }
        *reinterpret_cast<uint4*>(&ksm[j * 64 + ((c ^ (j & 7)) << 3)]) = kv;
        const __half* ve = reinterpret_cast<const __half*>(&vv);
#pragma unroll
        for (int e = 0; e < 8; ++e) {
            int ee = (e + c) & 7;                    // stagger to cut bank conflicts
            vsT[(8 * c + ee) * 264 + j] = ve[ee];
        }
    }
    __syncthreads();

    // ---- Q A-fragments: 4 k16-steps x 4 regs ----
    unsigned qa[4][4];
    {
        int m = m0 + g;
#pragma unroll
        for (int ks = 0; ks < 4; ++ks) {
            int base  = m * 64 + (((2 * ks) ^ (m & 7)) << 3) + 2 * tg;
            int base1 = m * 64 + (((2 * ks + 1) ^ (m & 7)) << 3) + 2 * tg;
            qa[ks][0] = *(const unsigned*)&qs[base];
            qa[ks][1] = *(const unsigned*)&qs[base + 512];
            qa[ks][2] = *(const unsigned*)&qs[base1];
            qa[ks][3] = *(const unsigned*)&qs[base1 + 512];
        }
    }

    // ---- S = Q @ K^T : 32 n-tiles x 4 k16-steps ----
    float s[32][4];
#pragma unroll
    for (int nt = 0; nt < 32; ++nt) {
        s[nt][0] = 0.f; s[nt][1] = 0.f; s[nt][2] = 0.f; s[nt][3] = 0.f;
        const int j = 8 * nt + g;
#pragma unroll
        for (int ks = 0; ks < 4; ++ks) {
            int base  = j * 64 + (((2 * ks) ^ g) << 3) + 2 * tg;
            int base1 = j * 64 + (((2 * ks + 1) ^ g) << 3) + 2 * tg;
            unsigned b0 = *(const unsigned*)&ksm[base];
            unsigned b1 = *(const unsigned*)&ksm[base1];
            mma_f16(s[nt], qa[ks][0], qa[ks][1], qa[ks][2], qa[ks][3], b0, b1);
        }
    }

    // ---- mask + softmax ----
    const int i_lo = m0 + g, i_hi = i_lo + 8;
    float mx0 = -3.0e38f, mx1 = -3.0e38f;
#pragma unroll
    for (int nt = 0; nt < 32; ++nt) {
        int j0 = 8 * nt + 2 * tg, j1 = j0 + 1;
        if (j0 > i_lo + WSZ) s[nt][0] = -1e10f;
        if (j1 > i_lo + WSZ) s[nt][1] = -1e10f;
        if (j0 > i_hi + WSZ) s[nt][2] = -1e10f;
        if (j1 > i_hi + WSZ) s[nt][3] = -1e10f;
        mx0 = fmaxf(mx0, fmaxf(s[nt][0], s[nt][1]));
        mx1 = fmaxf(mx1, fmaxf(s[nt][2], s[nt][3]));
    }
    mx0 = fmaxf(mx0, __shfl_xor_sync(0xffffffffu, mx0, 1));
    mx0 = fmaxf(mx0, __shfl_xor_sync(0xffffffffu, mx0, 2));
    mx1 = fmaxf(mx1, __shfl_xor_sync(0xffffffffu, mx1, 1));
    mx1 = fmaxf(mx1, __shfl_xor_sync(0xffffffffu, mx1, 2));

    float l0 = 0.f, l1 = 0.f;
    unsigned ph[32][2];                    // P fragments (half2 pairs)
#pragma unroll
    for (int nt = 0; nt < 32; ++nt) {
        float p0 = __expf(s[nt][0] - mx0);
        float p1 = __expf(s[nt][1] - mx0);
        float p2 = __expf(s[nt][2] - mx1);
        float p3 = __expf(s[nt][3] - mx1);
        l0 += p0 + p1;
        l1 += p2 + p3;
        ph[nt][0] = h2u(__floats2half2_rn(p0, p1));
        ph[nt][1] = h2u(__floats2half2_rn(p2, p3));
    }
    l0 += __shfl_xor_sync(0xffffffffu, l0, 1);
    l0 += __shfl_xor_sync(0xffffffffu, l0, 2);
    l1 += __shfl_xor_sync(0xffffffffu, l1, 1);
    l1 += __shfl_xor_sync(0xffffffffu, l1, 2);

    // ---- O = P @ V : 16 k16-steps x 8 n-tiles (P fragments direct, no shuffles) ----
    float ov[8][4];
#pragma unroll
    for (int nt = 0; nt < 8; ++nt) {
        ov[nt][0] = 0.f; ov[nt][1] = 0.f; ov[nt][2] = 0.f; ov[nt][3] = 0.f;
    }
#pragma unroll
    for (int kj = 0; kj < 16; ++kj) {
        unsigned a0 = ph[2 * kj][0];
        unsigned a1 = ph[2 * kj][1];
        unsigned a2 = ph[2 * kj + 1][0];
        unsigned a3 = ph[2 * kj + 1][1];
        const int kbase = 16 * kj + 2 * tg;
#pragma unroll
        for (int nt = 0; nt < 8; ++nt) {
            int d = 8 * nt + g;
            unsigned b0 = *(const unsigned*)&vsT[d * 264 + kbase];
            unsigned b1 = *(const unsigned*)&vsT[d * 264 + kbase + 8];
            mma_f16(ov[nt], a0, a1, a2, a3, b0, b1);
        }
    }

    // ---- normalize + write half ----
    float inv0 = 1.f / l0, inv1 = 1.f / l1;
    const int row_lo = tok0 + m0 + g;
#pragma unroll
    for (int nt = 0; nt < 8; ++nt) {
        int col = h * DHEAD + 8 * nt + 2 * tg;
        __half2 h0 = __floats2half2_rn(ov[nt][0] * inv0, ov[nt][1] * inv0);
        __half2 h1 = __floats2half2_rn(ov[nt][2] * inv1, ov[nt][3] * inv1);
        *reinterpret_cast<__half2*>(&o[(size_t)row_lo * HD + col]) = h0;
        *reinterpret_cast<__half2*>(&o[(size_t)(row_lo + 8) * HD + col]) = h1;
    }
}

// ---------------- launch ----------------
extern "C" void kernel_launch(void* const* d_in, const int* in_sizes, int n_in,
                              void* d_out, int out_size)
{
    (void)in_sizes; (void)n_in; (void)out_size;
    const float* x     = (const float*)d_in[0];  // [16384, 1024]
    const float* w_qkv = (const float*)d_in[1];  // [1024, 1536]
    const float* w_out = (const float*)d_in[2];  // [512, 1024]
    const float* b_out = (const float*)d_in[3];  // [1024]
    float*       out   = (float*)d_out;          // [16384, 1024]

    __half *xh, *wqkvT, *woutT, *qkvh, *attnh;
    cudaGetSymbolAddress((void**)&xh,    g_xh);
    cudaGetSymbolAddress((void**)&wqkvT, g_wqkvT);
    cudaGetSymbolAddress((void**)&woutT, g_woutT);
    cudaGetSymbolAddress((void**)&qkvh,  g_qkvh);
    cudaGetSymbolAddress((void**)&attnh, g_attnh);

    cudaFuncSetAttribute((const void*)h16gemm<false, true>,
                         cudaFuncAttributeMaxDynamicSharedMemorySize, HG_SMEM);
    cudaFuncSetAttribute((const void*)h16gemm<true, false>,
                         cudaFuncAttributeMaxDynamicSharedMemorySize, HG_SMEM);
    cudaFuncSetAttribute((const void*)attn_h16_kernel,
                         cudaFuncAttributeMaxDynamicSharedMemorySize, ATTN_SMEM_B);

    // 0) convert x -> half; transpose+convert weights -> half
    {
        int n4 = N_TOK * DIM / 4;
        cvt_f2h<<<(n4 + 255) / 256, 256>>>((const float4*)x, (__half2*)xh, n4);
        transpose_f2h<<<dim3(QKVW / 32, DIM / 32), dim3(32, 8)>>>(w_qkv, wqkvT, DIM, QKVW);
        transpose_f2h<<<dim3(DIM / 32, HD / 32),  dim3(32, 8)>>>(w_out, woutT, HD, DIM);
    }

    // 1) QKV projection: [16384,1024] @ [1024,1536], half out
    {
        dim3 grid(QKVW / 128, N_TOK / 128);
        h16gemm<false, true><<<grid, 256, HG_SMEM>>>(xh, wqkvT, nullptr, qkvh,
                                                     N_TOK, QKVW, DIM);
    }

    // 2) windowed look-back attention (fp16 mma, fp32 softmax)
    {
        dim3 grid(NWIN, HEADS);
        attn_h16_kernel<<<grid, 256, ATTN_SMEM_B>>>(qkvh, attnh);
    }

    // 3) output projection: [16384,512] @ [512,1024] + bias, fp32 out
    {
        dim3 grid(DIM / 128, N_TOK / 128);
        h16gemm<true, false><<<grid, 256, HG_SMEM>>>(attnh, woutT, b_out, out,
                                                     N_TOK, DIM, HD);
    }
}

// round 9
// speedup vs baseline: 2.1565x; 1.1408x over previous
#include <cuda_runtime.h>
#include <cuda_fp16.h>
#include <cstdint>

// ---------------- problem constants ----------------
#define N_TOK   16384
#define DIM     1024
#define HEADS   8
#define DHEAD   64
#define HD      (HEADS * DHEAD)   // 512
#define QKVW    (3 * HD)          // 1536
#define WSZ     128
#define NWIN    (N_TOK / WSZ)     // 128

// ---------------- scratch ----------------
__device__ __half g_xh[(size_t)N_TOK * DIM];      // x -> half
__device__ __half g_wqkvT[(size_t)QKVW * DIM];    // w_qkv^T half  [1536][1024]
__device__ __half g_woutT[(size_t)DIM * HD];      // w_out^T half  [1024][512]
__device__ __half g_qkvh[(size_t)N_TOK * QKVW];   // GEMM1 out half
__device__ __half g_attnh[(size_t)N_TOK * HD];    // attention out half

// ---------------- helpers ----------------
__device__ __forceinline__ unsigned h2u(__half2 h) {
    return *reinterpret_cast<unsigned*>(&h);
}

__device__ __forceinline__ void mma_f16(float c[4], unsigned a0, unsigned a1,
                                        unsigned a2, unsigned a3,
                                        unsigned b0, unsigned b1) {
    asm volatile(
        "mma.sync.aligned.m16n8k16.row.col.f32.f16.f16.f32 "
        "{%0,%1,%2,%3}, {%4,%5,%6,%7}, {%8,%9}, {%0,%1,%2,%3};"
        : "+f"(c[0]), "+f"(c[1]), "+f"(c[2]), "+f"(c[3])
        : "r"(a0), "r"(a1), "r"(a2), "r"(a3), "r"(b0), "r"(b1));
}

__device__ __forceinline__ void ldsm4(unsigned& r0, unsigned& r1,
                                      unsigned& r2, unsigned& r3, unsigned addr) {
    asm volatile("ldmatrix.sync.aligned.m8n8.x4.shared.b16 {%0,%1,%2,%3}, [%4];"
                 : "=r"(r0), "=r"(r1), "=r"(r2), "=r"(r3) : "r"(addr));
}

__global__ void cvt_f2h(const float4* __restrict__ in,
                        __half2* __restrict__ out, int n4)
{
    int i = blockIdx.x * blockDim.x + threadIdx.x;
    if (i < n4) {
        float4 v = in[i];
        out[2 * i + 0] = __floats2half2_rn(v.x, v.y);
        out[2 * i + 1] = __floats2half2_rn(v.z, v.w);
    }
}

// in[R][C] fp32 -> out[C][R] half. block (32,8), grid (C/32, R/32).
__global__ void transpose_f2h(const float* __restrict__ in,
                              __half* __restrict__ out, int R, int C)
{
    __shared__ float t[32][33];
    int bx = blockIdx.x * 32, by = blockIdx.y * 32;
    int x = bx + threadIdx.x;
#pragma unroll
    for (int i = 0; i < 32; i += 8) {
        int y = by + threadIdx.y + i;
        t[threadIdx.y + i][threadIdx.x] = in[(size_t)y * C + x];
    }
    __syncthreads();
    int xo = by + threadIdx.x;
#pragma unroll
    for (int i = 0; i < 32; i += 8) {
        int yo = bx + threadIdx.y + i;
        out[(size_t)yo * R + xo] = __float2half_rn(t[threadIdx.x][threadIdx.y + i]);
    }
}

// ---------------- FP16 tensor-core GEMM ----------------
// C[M,N] = A[M,K] @ Bt[N,K]^T (+bias). A, Bt half row-major.
// CTA 128x128x64(halves), 8 warps 2x4 (warp tile 64x32), 3-stage cp.async,
// ldmatrix.x4 fragment loads. smem row r = 64 halves, 16B chunk c at c^(r&7).
#define CPA16(dst, src) \
    asm volatile("cp.async.cg.shared.global [%0], [%1], 16;" :: "r"(dst), "l"(src))

#define HSTAGE 16384                       // halves per stage
#define HG_SMEM (3 * HSTAGE * 2)           // 98304 bytes

template <bool WITH_BIAS, bool HALF_OUT>
__global__ __launch_bounds__(256, 2)
void h16gemm(const __half* __restrict__ A, const __half* __restrict__ Bt,
             const float* __restrict__ bias, void* __restrict__ Cout,
             int M, int N, int K)
{
    extern __shared__ __half hsm[];
    const unsigned smBase = (unsigned)__cvta_generic_to_shared(hsm);

    const int tid  = threadIdx.x;
    const int lane = tid & 31;
    const int wid  = tid >> 5;
    const int wm   = wid >> 2;          // 0..1
    const int wn   = wid & 3;           // 0..3
    const int g    = lane >> 2;         // 0..7
    const int tg   = lane & 3;          // 0..3

    const int row0 = blockIdx.y * 128;
    const int col0 = blockIdx.x * 128;
    const int NKT  = K / 64;

    float acc[4][4][4];
#pragma unroll
    for (int mi = 0; mi < 4; ++mi)
#pragma unroll
        for (int ni = 0; ni < 4; ++ni)
#pragma unroll
            for (int r = 0; r < 4; ++r) acc[mi][ni][r] = 0.f;

    auto issue = [&](int kt, int s) {
        const unsigned sb = smBase + (unsigned)s * (HSTAGE * 2);
#pragma unroll
        for (int p = 0; p < 4; ++p) {       // A: 1024 chunks / 256 thr
            int idx = p * 256 + tid;
            int r = idx >> 3, c = idx & 7;
            CPA16(sb + (unsigned)(r * 128 + ((c ^ (r & 7)) * 16)),
                  A + (size_t)(row0 + r) * K + kt * 64 + c * 8);
        }
#pragma unroll
        for (int p = 0; p < 4; ++p) {       // B: 1024 chunks
            int idx = p * 256 + tid;
            int r = idx >> 3, c = idx & 7;
            CPA16(sb + 16384u + (unsigned)(r * 128 + ((c ^ (r & 7)) * 16)),
                  Bt + (size_t)(col0 + r) * K + kt * 64 + c * 8);
        }
        asm volatile("cp.async.commit_group;");
    };

    issue(0, 0);
    issue(1, 1);

    // ldmatrix lane decomposition (constant per thread)
    const int lr  = lane & 15;          // row-in-tile for A
    const int lc  = lane >> 4;          // chunk parity for A / +8 n-offset for B
    const int bn8 = 8 * (lane >> 4) + (lane & 7);   // B row offset within 16
    const int bcp = (lane >> 3) & 1;                // B chunk parity

    for (int kt = 0; kt < NKT; ++kt) {
        const int s = kt % 3;
        if (kt + 1 < NKT) asm volatile("cp.async.wait_group 1;");
        else              asm volatile("cp.async.wait_group 0;");
        __syncthreads();
        if (kt + 2 < NKT) issue(kt + 2, (kt + 2) % 3);

        const unsigned sA = smBase + (unsigned)s * (HSTAGE * 2);
        const unsigned sB = sA + 16384u;

#pragma unroll
        for (int ks = 0; ks < 4; ++ks) {
            unsigned a[4][4];
#pragma unroll
            for (int mi = 0; mi < 4; ++mi) {
                int m = wm * 64 + mi * 16 + lr;
                int c = 2 * ks + lc;
                ldsm4(a[mi][0], a[mi][1], a[mi][2], a[mi][3],
                      sA + (unsigned)(2 * (m * 64 + ((c ^ (m & 7)) << 3))));
            }
            unsigned b[4][2];
#pragma unroll
            for (int blk = 0; blk < 2; ++blk) {
                int n = wn * 32 + 16 * blk + bn8;
                int c = 2 * ks + bcp;
                ldsm4(b[2 * blk][0], b[2 * blk][1], b[2 * blk + 1][0], b[2 * blk + 1][1],
                      sB + (unsigned)(2 * (n * 64 + ((c ^ (n & 7)) << 3))));
            }
#pragma unroll
            for (int mi = 0; mi < 4; ++mi)
#pragma unroll
                for (int ni = 0; ni < 4; ++ni)
                    mma_f16(acc[mi][ni], a[mi][0], a[mi][1], a[mi][2], a[mi][3],
                            b[ni][0], b[ni][1]);
        }
        __syncthreads();
    }

    // epilogue
#pragma unroll
    for (int ni = 0; ni < 4; ++ni) {
        int col = col0 + wn * 32 + ni * 8 + 2 * tg;
        float bx = 0.f, by = 0.f;
        if (WITH_BIAS) { bx = bias[col]; by = bias[col + 1]; }
#pragma unroll
        for (int mi = 0; mi < 4; ++mi) {
            int row = row0 + wm * 64 + mi * 16 + g;
            if (HALF_OUT) {
                __half* C = (__half*)Cout;
                __half2 h0 = __floats2half2_rn(acc[mi][ni][0], acc[mi][ni][1]);
                __half2 h1 = __floats2half2_rn(acc[mi][ni][2], acc[mi][ni][3]);
                *reinterpret_cast<__half2*>(&C[(size_t)row * N + col]) = h0;
                *reinterpret_cast<__half2*>(&C[(size_t)(row + 8) * N + col]) = h1;
            } else {
                float* C = (float*)Cout;
                float2 v0 = make_float2(acc[mi][ni][0] + bx, acc[mi][ni][1] + by);
                float2 v1 = make_float2(acc[mi][ni][2] + bx, acc[mi][ni][3] + by);
                *reinterpret_cast<float2*>(&C[(size_t)row * N + col]) = v0;
                *reinterpret_cast<float2*>(&C[(size_t)(row + 8) * N + col]) = v1;
            }
        }
    }
}

// ---------------- FP16 tensor-core attention ----------------
// One CTA per (window, head), 256 threads (8 warps x 16 query rows).
// smem (halves): qs [128][64] swizzled @0; ksm [256][64] swizzled @8192;
//                vsT [64][264] (V transposed, padded) @24576.
#define ATTN_SMEM_H (24576 + 64 * 264)            // halves
#define ATTN_SMEM_B (ATTN_SMEM_H * 2)             // 82944 bytes

__global__ __launch_bounds__(256, 1)
void attn_h16_kernel(const __half* __restrict__ qkv, __half* __restrict__ o)
{
    extern __shared__ __half hs[];
    __half* qs  = hs;
    __half* ksm = hs + 8192;
    __half* vsT = hs + 24576;

    const int w    = blockIdx.x;
    const int h    = blockIdx.y;
    const int tid  = threadIdx.x;
    const int lane = tid & 31;
    const int wq   = tid >> 5;
    const int g    = lane >> 2;
    const int tg   = lane & 3;
    const int m0   = wq * 16;
    const int tok0 = w * WSZ;

    const unsigned qsB  = (unsigned)__cvta_generic_to_shared(qs);
    const unsigned ksmB = (unsigned)__cvta_generic_to_shared(ksm);
    const unsigned vsTB = (unsigned)__cvta_generic_to_shared(vsT);

    const __half2 qscale = __floats2half2_rn(0.125f, 0.125f);

    // ---- load Q (scaled), swizzled ----
#pragma unroll
    for (int p = 0; p < 4; ++p) {                    // 1024 chunks
        int idx = p * 256 + tid;
        int row = idx >> 3, c = idx & 7;
        uint4 v = *reinterpret_cast<const uint4*>(
            &qkv[(size_t)(tok0 + row) * QKVW + h * DHEAD + c * 8]);
        __half2* hv = reinterpret_cast<__half2*>(&v);
        hv[0] = __hmul2(hv[0], qscale);
        hv[1] = __hmul2(hv[1], qscale);
        hv[2] = __hmul2(hv[2], qscale);
        hv[3] = __hmul2(hv[3], qscale);
        *reinterpret_cast<uint4*>(&qs[row * 64 + ((c ^ (row & 7)) << 3)]) = v;
    }

    // ---- load K (swizzled) and V (transposed into vsT) ----
#pragma unroll
    for (int p = 0; p < 8; ++p) {                    // 2048 chunks
        int idx = p * 256 + tid;
        int j = idx >> 3, c = idx & 7;
        uint4 kv = make_uint4(0, 0, 0, 0), vv = make_uint4(0, 0, 0, 0);
        if (!(w == 0 && j < WSZ)) {
            size_t tok = (size_t)(tok0 - WSZ + j);
            kv = *reinterpret_cast<const uint4*>(&qkv[tok * QKVW +     HD + h * DHEAD + c * 8]);
            vv = *reinterpret_cast<const uint4*>(&qkv[tok * QKVW + 2 * HD + h * DHEAD + c * 8]);
        }
        *reinterpret_cast<uint4*>(&ksm[j * 64 + ((c ^ (j & 7)) << 3)]) = kv;
        const __half* ve = reinterpret_cast<const __half*>(&vv);
#pragma unroll
        for (int e = 0; e < 8; ++e) {
            int ee = (e + c) & 7;                    // stagger to cut bank conflicts
            vsT[(8 * c + ee) * 264 + j] = ve[ee];
        }
    }
    __syncthreads();

    // ldmatrix lane decomposition
    const int lr  = lane & 15;
    const int lc  = lane >> 4;
    const int bn8 = 8 * (lane >> 4) + (lane & 7);
    const int bcp = (lane >> 3) & 1;

    // ---- Q A-fragments: 4 k16-steps via ldmatrix.x4 ----
    unsigned qa[4][4];
#pragma unroll
    for (int ks = 0; ks < 4; ++ks) {
        int m = m0 + lr;
        int c = 2 * ks + lc;
        ldsm4(qa[ks][0], qa[ks][1], qa[ks][2], qa[ks][3],
              qsB + (unsigned)(2 * (m * 64 + ((c ^ (m & 7)) << 3))));
    }

    // ---- S = Q @ K^T : 16 nt-pairs x 4 k16-steps (ldmatrix.x4 B) ----
    float s[32][4];
#pragma unroll
    for (int nt = 0; nt < 32; ++nt) {
        s[nt][0] = 0.f; s[nt][1] = 0.f; s[nt][2] = 0.f; s[nt][3] = 0.f;
    }
#pragma unroll
    for (int ntp = 0; ntp < 16; ++ntp) {
        const int jb = 16 * ntp + bn8;
#pragma unroll
        for (int ks = 0; ks < 4; ++ks) {
            int c = 2 * ks + bcp;
            unsigned b0, b1, b2, b3;
            ldsm4(b0, b1, b2, b3,
                  ksmB + (unsigned)(2 * (jb * 64 + ((c ^ (jb & 7)) << 3))));
            mma_f16(s[2 * ntp],     qa[ks][0], qa[ks][1], qa[ks][2], qa[ks][3], b0, b1);
            mma_f16(s[2 * ntp + 1], qa[ks][0], qa[ks][1], qa[ks][2], qa[ks][3], b2, b3);
        }
    }

    // ---- mask + softmax ----
    const int i_lo = m0 + g, i_hi = i_lo + 8;
    float mx0 = -3.0e38f, mx1 = -3.0e38f;
#pragma unroll
    for (int nt = 0; nt < 32; ++nt) {
        int j0 = 8 * nt + 2 * tg, j1 = j0 + 1;
        if (j0 > i_lo + WSZ) s[nt][0] = -1e10f;
        if (j1 > i_lo + WSZ) s[nt][1] = -1e10f;
        if (j0 > i_hi + WSZ) s[nt][2] = -1e10f;
        if (j1 > i_hi + WSZ) s[nt][3] = -1e10f;
        mx0 = fmaxf(mx0, fmaxf(s[nt][0], s[nt][1]));
        mx1 = fmaxf(mx1, fmaxf(s[nt][2], s[nt][3]));
    }
    mx0 = fmaxf(mx0, __shfl_xor_sync(0xffffffffu, mx0, 1));
    mx0 = fmaxf(mx0, __shfl_xor_sync(0xffffffffu, mx0, 2));
    mx1 = fmaxf(mx1, __shfl_xor_sync(0xffffffffu, mx1, 1));
    mx1 = fmaxf(mx1, __shfl_xor_sync(0xffffffffu, mx1, 2));

    float l0 = 0.f, l1 = 0.f;
    unsigned ph[32][2];                    // P fragments (half2 pairs)
#pragma unroll
    for (int nt = 0; nt < 32; ++nt) {
        float p0 = __expf(s[nt][0] - mx0);
        float p1 = __expf(s[nt][1] - mx0);
        float p2 = __expf(s[nt][2] - mx1);
        float p3 = __expf(s[nt][3] - mx1);
        l0 += p0 + p1;
        l1 += p2 + p3;
        ph[nt][0] = h2u(__floats2half2_rn(p0, p1));
        ph[nt][1] = h2u(__floats2half2_rn(p2, p3));
    }
    l0 += __shfl_xor_sync(0xffffffffu, l0, 1);
    l0 += __shfl_xor_sync(0xffffffffu, l0, 2);
    l1 += __shfl_xor_sync(0xffffffffu, l1, 1);
    l1 += __shfl_xor_sync(0xffffffffu, l1, 2);

    // ---- O = P @ V : 16 k16-steps x 4 nt-pairs (ldmatrix.x4 V) ----
    float ov[8][4];
#pragma unroll
    for (int nt = 0; nt < 8; ++nt) {
        ov[nt][0] = 0.f; ov[nt][1] = 0.f; ov[nt][2] = 0.f; ov[nt][3] = 0.f;
    }
#pragma unroll
    for (int kj = 0; kj < 16; ++kj) {
        unsigned a0 = ph[2 * kj][0];
        unsigned a1 = ph[2 * kj][1];
        unsigned a2 = ph[2 * kj + 1][0];
        unsigned a3 = ph[2 * kj + 1][1];
#pragma unroll
        for (int ntp = 0; ntp < 4; ++ntp) {
            int d = 16 * ntp + bn8;
            int koff = 16 * kj + 8 * bcp;
            unsigned b0, b1, b2, b3;
            ldsm4(b0, b1, b2, b3,
                  vsTB + (unsigned)(2 * (d * 264 + koff)));
            mma_f16(ov[2 * ntp],     a0, a1, a2, a3, b0, b1);
            mma_f16(ov[2 * ntp + 1], a0, a1, a2, a3, b2, b3);
        }
    }

    // ---- normalize + write half ----
    float inv0 = 1.f / l0, inv1 = 1.f / l1;
    const int row_lo = tok0 + m0 + g;
#pragma unroll
    for (int nt = 0; nt < 8; ++nt) {
        int col = h * DHEAD + 8 * nt + 2 * tg;
        __half2 h0 = __floats2half2_rn(ov[nt][0] * inv0, ov[nt][1] * inv0);
        __half2 h1 = __floats2half2_rn(ov[nt][2] * inv1, ov[nt][3] * inv1);
        *reinterpret_cast<__half2*>(&o[(size_t)row_lo * HD + col]) = h0;
        *reinterpret_cast<__half2*>(&o[(size_t)(row_lo + 8) * HD + col]) = h1;
    }
}

// ---------------- launch ----------------
extern "C" void kernel_launch(void* const* d_in, const int* in_sizes, int n_in,
                              void* d_out, int out_size)
{
    (void)in_sizes; (void)n_in; (void)out_size;
    const float* x     = (const float*)d_in[0];  // [16384, 1024]
    const float* w_qkv = (const float*)d_in[1];  // [1024, 1536]
    const float* w_out = (const float*)d_in[2];  // [512, 1024]
    const float* b_out = (const float*)d_in[3];  // [1024]
    float*       out   = (float*)d_out;          // [16384, 1024]

    __half *xh, *wqkvT, *woutT, *qkvh, *attnh;
    cudaGetSymbolAddress((void**)&xh,    g_xh);
    cudaGetSymbolAddress((void**)&wqkvT, g_wqkvT);
    cudaGetSymbolAddress((void**)&woutT, g_woutT);
    cudaGetSymbolAddress((void**)&qkvh,  g_qkvh);
    cudaGetSymbolAddress((void**)&attnh, g_attnh);

    cudaFuncSetAttribute((const void*)h16gemm<false, true>,
                         cudaFuncAttributeMaxDynamicSharedMemorySize, HG_SMEM);
    cudaFuncSetAttribute((const void*)h16gemm<true, false>,
                         cudaFuncAttributeMaxDynamicSharedMemorySize, HG_SMEM);
    cudaFuncSetAttribute((const void*)attn_h16_kernel,
                         cudaFuncAttributeMaxDynamicSharedMemorySize, ATTN_SMEM_B);

    // 0) convert x -> half; transpose+convert weights -> half
    {
        int n4 = N_TOK * DIM / 4;
        cvt_f2h<<<(n4 + 255) / 256, 256>>>((const float4*)x, (__half2*)xh, n4);
        transpose_f2h<<<dim3(QKVW / 32, DIM / 32), dim3(32, 8)>>>(w_qkv, wqkvT, DIM, QKVW);
        transpose_f2h<<<dim3(DIM / 32, HD / 32),  dim3(32, 8)>>>(w_out, woutT, HD, DIM);
    }

    // 1) QKV projection: [16384,1024] @ [1024,1536], half out
    {
        dim3 grid(QKVW / 128, N_TOK / 128);
        h16gemm<false, true><<<grid, 256, HG_SMEM>>>(xh, wqkvT, nullptr, qkvh,
                                                     N_TOK, QKVW, DIM);
    }

    // 2) windowed look-back attention (fp16 mma, fp32 softmax)
    {
        dim3 grid(NWIN, HEADS);
        attn_h16_kernel<<<grid, 256, ATTN_SMEM_B>>>(qkvh, attnh);
    }

    // 3) output projection: [16384,512] @ [512,1024] + bias, fp32 out
    {
        dim3 grid(DIM / 128, N_TOK / 128);
        h16gemm<true, false><<<grid, 256, HG_SMEM>>>(attnh, woutT, b_out, out,
                                                     N_TOK, DIM, HD);
    }
}